// round 5
// baseline (speedup 1.0000x reference)
#include <cuda_runtime.h>
#include <mma.h>

using namespace nvcuda;

#define T_  512
#define B_  64
#define H_  1024
#define G_  4096
#define BH  (B_*H_)
#define TBH ((size_t)T_*B_*H_)
#define NCTA 128

// ---------------- device scratch (no allocations allowed) ----------------
__device__ float    g_xin[(size_t)T_*B_*G_];   // per-layer input projection (reused)
__device__ float    g_seq0[(size_t)T_*B_*H_];  // layer-0 output sequence
__device__ float    g_h[2*BH];                 // double-buffered h state
__device__ unsigned g_ctr[2];                  // per-layer step barrier counters

// Shared-memory plan for the persistent recurrence kernel (floats):
//  Ws   32x1032  (w_hh slice, tf32-rounded, padded)      off 0
//  Hs   64x264   (h chunk staging)                       off 33024
//  Gs   64x36    (gate GEMM result)                      off 49920
//  Cs   512      (resident c state)                      off 52224
//  Bsum 32       (b_ih + b_hh for owned rows)            off 52736
#define SMEM_FLOATS 52768
#define SMEM_BYTES  (SMEM_FLOATS*4)

// ---------------- init: zero h buffers + barrier counters ----------------
__global__ void init_kernel() {
    int i = blockIdx.x * blockDim.x + threadIdx.x;   // 128*256 = 32768 threads
    #pragma unroll
    for (int k = 0; k < 4; k++) {
        int idx = i + k * 32768;
        g_h[idx] = 0.0f;                              // 2*BH = 131072 = 4*32768
    }
    if (i < 2) g_ctr[i] = 0u;
}

// ---------------- Stage 1: xin[M=32768, N=4096] = A[M,1024] @ W[4096,1024]^T ----------
__global__ __launch_bounds__(256) void gemm_xin(const float* __restrict__ x,
                                                const float* __restrict__ wih,
                                                int layer) {
    const float* A = (layer == 0) ? x : g_seq0;
    const float* W = wih + (size_t)layer * (size_t)G_ * H_;

    __shared__ float As[128*40];
    __shared__ float Bs2[64*40];

    const int tid  = threadIdx.x;
    const int warp = tid >> 5;
    const int wm   = warp & 3;          // M subtile (32 rows)
    const int wn   = warp >> 2;         // N subtile (32 cols)
    const size_t m0 = (size_t)blockIdx.y * 128;
    const int    n0 = blockIdx.x * 64;

    wmma::fragment<wmma::accumulator,16,16,8,float> acc[2][2];
    #pragma unroll
    for (int mi = 0; mi < 2; mi++)
        #pragma unroll
        for (int ni = 0; ni < 2; ni++)
            wmma::fill_fragment(acc[mi][ni], 0.0f);

    for (int kc = 0; kc < 1024; kc += 32) {
        #pragma unroll
        for (int i = 0; i < 4; i++) {
            int idx = i*256 + tid;
            int r = idx >> 3, c = (idx & 7) << 2;
            float4 v = *reinterpret_cast<const float4*>(&A[(m0 + r)*1024 + kc + c]);
            v.x = wmma::__float_to_tf32(v.x); v.y = wmma::__float_to_tf32(v.y);
            v.z = wmma::__float_to_tf32(v.z); v.w = wmma::__float_to_tf32(v.w);
            *reinterpret_cast<float4*>(&As[r*40 + c]) = v;
        }
        #pragma unroll
        for (int i = 0; i < 2; i++) {
            int idx = i*256 + tid;
            int r = idx >> 3, c = (idx & 7) << 2;
            float4 v = *reinterpret_cast<const float4*>(&W[(size_t)(n0 + r)*1024 + kc + c]);
            v.x = wmma::__float_to_tf32(v.x); v.y = wmma::__float_to_tf32(v.y);
            v.z = wmma::__float_to_tf32(v.z); v.w = wmma::__float_to_tf32(v.w);
            *reinterpret_cast<float4*>(&Bs2[r*40 + c]) = v;
        }
        __syncthreads();
        #pragma unroll
        for (int k8 = 0; k8 < 4; k8++) {
            wmma::fragment<wmma::matrix_a,16,16,8,wmma::precision::tf32,wmma::row_major> af[2];
            wmma::fragment<wmma::matrix_b,16,16,8,wmma::precision::tf32,wmma::col_major> bf[2];
            #pragma unroll
            for (int mi = 0; mi < 2; mi++)
                wmma::load_matrix_sync(af[mi], &As[(wm*32 + mi*16)*40 + k8*8], 40);
            #pragma unroll
            for (int ni = 0; ni < 2; ni++)
                wmma::load_matrix_sync(bf[ni], &Bs2[(wn*32 + ni*16)*40 + k8*8], 40);
            #pragma unroll
            for (int mi = 0; mi < 2; mi++)
                #pragma unroll
                for (int ni = 0; ni < 2; ni++)
                    wmma::mma_sync(acc[mi][ni], af[mi], bf[ni], acc[mi][ni]);
        }
        __syncthreads();
    }
    #pragma unroll
    for (int mi = 0; mi < 2; mi++)
        #pragma unroll
        for (int ni = 0; ni < 2; ni++)
            wmma::store_matrix_sync(
                &g_xin[(m0 + wm*32 + mi*16)*(size_t)G_ + n0 + wn*32 + ni*16],
                acc[mi][ni], G_, wmma::mem_row_major);
}

// ---------------- Stage 2: persistent recurrence, 128 co-resident CTAs ----------------
// CTA owns h-columns [j0, j0+8) across all 4 gates (32 w_hh rows, smem-resident).
__global__ __launch_bounds__(256) void lstm_rec(const float* __restrict__ whh,
                                                const float* __restrict__ bih,
                                                const float* __restrict__ bhh,
                                                float* __restrict__ out,
                                                int layer) {
    extern __shared__ float sm[];
    float* Ws   = sm;                    // 32 x 1032
    float* Hs   = sm + 33024;            // 64 x 264
    float* Gs   = sm + 49920;            // 64 x 36
    float* Cs   = sm + 52224;            // 512
    float* Bsum = sm + 52736;            // 32

    const int tid  = threadIdx.x;
    const int warp = tid >> 5;
    const int wm   = warp & 3;           // batch subtile (16 rows)
    const int wn   = warp >> 2;          // gate-col subtile (16 cols)
    const int j0   = blockIdx.x * 8;

    const float* whh_l = whh + (size_t)layer * (size_t)G_ * H_;
    const float* bih_l = bih + (size_t)layer * G_;
    const float* bhh_l = bhh + (size_t)layer * G_;
    float* seq_out = (layer == 0) ? g_seq0 : out;
    float* hn_out  = out + TBH + (size_t)layer * BH;
    float* cn_out  = out + TBH + 2*(size_t)BH + (size_t)layer * BH;
    unsigned* ctr  = &g_ctr[layer];

    // Stage the 32 w_hh rows (gate order i,f,g,o -> smem cols 0..31), tf32-rounded.
    #pragma unroll 4
    for (int i = 0; i < 32; i++) {
        int idx = i*256 + tid;           // 8192 float4
        int r = idx >> 8;                // 0..31
        int c = (idx & 255) << 2;        // 0..1020
        int grow = (r >> 3) * H_ + j0 + (r & 7);
        float4 v = *reinterpret_cast<const float4*>(&whh_l[(size_t)grow * H_ + c]);
        v.x = wmma::__float_to_tf32(v.x); v.y = wmma::__float_to_tf32(v.y);
        v.z = wmma::__float_to_tf32(v.z); v.w = wmma::__float_to_tf32(v.w);
        *reinterpret_cast<float4*>(&Ws[r*1032 + c]) = v;
    }
    if (tid < 32) {
        int grow = (tid >> 3) * H_ + j0 + (tid & 7);
        Bsum[tid] = bih_l[grow] + bhh_l[grow];
    }
    Cs[tid] = 0.0f; Cs[tid + 256] = 0.0f;
    __syncthreads();

    for (int t = 0; t < T_; ++t) {
        const float* hprev = g_h + (size_t)(t & 1) * BH;
        float*       hnext = g_h + (size_t)((t + 1) & 1) * BH;

        wmma::fragment<wmma::accumulator,16,16,8,float> acc;
        wmma::fill_fragment(acc, 0.0f);

        for (int kc = 0; kc < H_; kc += 256) {
            // stage h chunk [64 x 256], L2-only loads (L1 may be stale across steps)
            #pragma unroll 4
            for (int i = 0; i < 16; i++) {
                int idx = i*256 + tid;   // 4096 float4
                int r = idx >> 6;        // 0..63
                int c = (idx & 63) << 2; // 0..252
                float4 v = __ldcg(reinterpret_cast<const float4*>(&hprev[(size_t)r*H_ + kc + c]));
                v.x = wmma::__float_to_tf32(v.x); v.y = wmma::__float_to_tf32(v.y);
                v.z = wmma::__float_to_tf32(v.z); v.w = wmma::__float_to_tf32(v.w);
                *reinterpret_cast<float4*>(&Hs[r*264 + c]) = v;
            }
            __syncthreads();
            #pragma unroll 8
            for (int k8 = 0; k8 < 32; k8++) {
                wmma::fragment<wmma::matrix_a,16,16,8,wmma::precision::tf32,wmma::row_major> af;
                wmma::fragment<wmma::matrix_b,16,16,8,wmma::precision::tf32,wmma::col_major> bf;
                wmma::load_matrix_sync(af, &Hs[(wm*16)*264 + k8*8], 264);
                wmma::load_matrix_sync(bf, &Ws[(wn*16)*1032 + kc + k8*8], 1032);
                wmma::mma_sync(acc, af, bf, acc);
            }
            __syncthreads();
        }

        wmma::store_matrix_sync(&Gs[(wm*16)*36 + wn*16], acc, 36, wmma::mem_row_major);
        __syncthreads();

        // fused gate epilogue: 512 (b, jj) elements over 256 threads
        #pragma unroll
        for (int e = tid; e < 512; e += 256) {
            int b = e >> 3, jj = e & 7;
            const float* xrow = g_xin + ((size_t)t * B_ + b) * G_ + j0;
            float gi = Gs[b*36 + jj]      + xrow[jj]        + Bsum[jj];
            float gf = Gs[b*36 + 8 + jj]  + xrow[1024 + jj] + Bsum[8 + jj];
            float gg = Gs[b*36 + 16 + jj] + xrow[2048 + jj] + Bsum[16 + jj];
            float go = Gs[b*36 + 24 + jj] + xrow[3072 + jj] + Bsum[24 + jj];
            float si = 1.0f / (1.0f + __expf(-gi));
            float sf = 1.0f / (1.0f + __expf(-gf));
            float so = 1.0f / (1.0f + __expf(-go));
            float cv = sf * Cs[e] + si * tanhf(gg);
            float hv = so * tanhf(cv);
            Cs[e] = cv;
            hnext[(size_t)b*H_ + j0 + jj] = hv;
            seq_out[((size_t)t * B_ + b) * H_ + j0 + jj] = hv;
            if (t == T_ - 1) {
                hn_out[(size_t)b*H_ + j0 + jj] = hv;
                cn_out[(size_t)b*H_ + j0 + jj] = cv;
            }
        }
        __syncthreads();

        // global step barrier: monotonic counter, release(threadfence) / acquire(volatile)
        if (tid == 0) {
            __threadfence();
            atomicAdd(ctr, 1u);
            unsigned tgt = (unsigned)NCTA * (unsigned)(t + 1);
            while (*reinterpret_cast<volatile unsigned*>(ctr) < tgt) __nanosleep(32);
        }
        __syncthreads();
    }
}

// ---------------- launch ----------------
extern "C" void kernel_launch(void* const* d_in, const int* in_sizes, int n_in,
                              void* d_out, int out_size) {
    const float* x   = (const float*)d_in[0];
    const float* wih = (const float*)d_in[1];
    const float* whh = (const float*)d_in[2];
    const float* bih = (const float*)d_in[3];
    const float* bhh = (const float*)d_in[4];
    float* out = (float*)d_out;

    cudaFuncSetAttribute(lstm_rec, cudaFuncAttributeMaxDynamicSharedMemorySize, SMEM_BYTES);

    // layer 0
    init_kernel<<<128, 256>>>();
    gemm_xin<<<dim3(64, 256), 256>>>(x, wih, 0);
    lstm_rec<<<NCTA, 256, SMEM_BYTES>>>(whh, bih, bhh, out, 0);
    // layer 1 (reset h buffers + counters; consumes g_seq0)
    init_kernel<<<128, 256>>>();
    gemm_xin<<<dim3(64, 256), 256>>>(x, wih, 1);
    lstm_rec<<<NCTA, 256, SMEM_BYTES>>>(whh, bih, bhh, out, 1);
}

// round 6
// speedup vs baseline: 1.1874x; 1.1874x over previous
#include <cuda_runtime.h>
#include <mma.h>

using namespace nvcuda;

#define T_  512
#define B_  64
#define H_  1024
#define G_  4096
#define BH  (B_*H_)
#define TBH ((size_t)T_*B_*H_)
#define NCTA 128

// ---------------- device scratch (no allocations allowed) ----------------
__device__ float    g_xin[(size_t)T_*B_*G_];   // per-layer input projection (reused)
__device__ float    g_seq0[(size_t)T_*B_*H_];  // layer-0 output sequence
__device__ float    g_h[2*BH];                 // double-buffered h state
__device__ unsigned g_flag[NCTA];              // per-CTA step flags

// Shared plan for lstm_rec (floats):
//  Ws   32 x 1032   off 0       (w_hh slice, tf32, padded)
//  Hs   64 x 136    off 33024   (h chunk staging, kc=128)
//  Ps   8 x 32 x 36 off 41728   (per-warp partial tiles)
//  Cs   512         off 50944   (resident c state)
//  Bsum 32          off 51456
#define OFF_HS  33024
#define OFF_PS  41728
#define OFF_CS  50944
#define OFF_BS  51456
#define SMEM_FLOATS 51488
#define SMEM_BYTES  (SMEM_FLOATS*4)

// ---------------- init: zero h buffers + flags ----------------
__global__ void init_kernel() {
    int i = blockIdx.x * blockDim.x + threadIdx.x;   // 32768 threads
    #pragma unroll
    for (int k = 0; k < 4; k++) g_h[i + k * 32768] = 0.0f;
    if (i < NCTA) g_flag[i] = 0u;
}

// ---------------- Stage 1: xin[32768,4096] = A[32768,1024] @ W[4096,1024]^T ------
// CTA tile 128x128, kc=32. 8 warps = 2(M) x 4(N), warp tile 64x32.
__global__ __launch_bounds__(256) void gemm_xin(const float* __restrict__ x,
                                                const float* __restrict__ wih,
                                                int layer) {
    const float* A = (layer == 0) ? x : g_seq0;
    const float* W = wih + (size_t)layer * (size_t)G_ * H_;

    __shared__ float As[128*40];
    __shared__ float Bs[128*40];

    const int tid  = threadIdx.x;
    const int warp = tid >> 5;
    const int wm   = warp >> 2;         // 0..1 : 64 M-rows
    const int wn   = warp & 3;          // 0..3 : 32 N-cols
    const size_t m0 = (size_t)blockIdx.y * 128;
    const int    n0 = blockIdx.x * 128;

    wmma::fragment<wmma::accumulator,16,16,8,float> acc[4][2];
    #pragma unroll
    for (int mi = 0; mi < 4; mi++)
        #pragma unroll
        for (int ni = 0; ni < 2; ni++)
            wmma::fill_fragment(acc[mi][ni], 0.0f);

    for (int kc = 0; kc < 1024; kc += 32) {
        #pragma unroll
        for (int i = 0; i < 4; i++) {
            int idx = i*256 + tid;
            int r = idx >> 3, c = (idx & 7) << 2;
            float4 v = *reinterpret_cast<const float4*>(&A[(m0 + r)*1024 + kc + c]);
            v.x = wmma::__float_to_tf32(v.x); v.y = wmma::__float_to_tf32(v.y);
            v.z = wmma::__float_to_tf32(v.z); v.w = wmma::__float_to_tf32(v.w);
            *reinterpret_cast<float4*>(&As[r*40 + c]) = v;
            float4 w4 = *reinterpret_cast<const float4*>(&W[(size_t)(n0 + r)*1024 + kc + c]);
            w4.x = wmma::__float_to_tf32(w4.x); w4.y = wmma::__float_to_tf32(w4.y);
            w4.z = wmma::__float_to_tf32(w4.z); w4.w = wmma::__float_to_tf32(w4.w);
            *reinterpret_cast<float4*>(&Bs[r*40 + c]) = w4;
        }
        __syncthreads();
        #pragma unroll
        for (int k8 = 0; k8 < 4; k8++) {
            wmma::fragment<wmma::matrix_a,16,16,8,wmma::precision::tf32,wmma::row_major> af[4];
            wmma::fragment<wmma::matrix_b,16,16,8,wmma::precision::tf32,wmma::col_major> bf[2];
            #pragma unroll
            for (int mi = 0; mi < 4; mi++)
                wmma::load_matrix_sync(af[mi], &As[(wm*64 + mi*16)*40 + k8*8], 40);
            #pragma unroll
            for (int ni = 0; ni < 2; ni++)
                wmma::load_matrix_sync(bf[ni], &Bs[(wn*32 + ni*16)*40 + k8*8], 40);
            #pragma unroll
            for (int mi = 0; mi < 4; mi++)
                #pragma unroll
                for (int ni = 0; ni < 2; ni++)
                    wmma::mma_sync(acc[mi][ni], af[mi], bf[ni], acc[mi][ni]);
        }
        __syncthreads();
    }
    #pragma unroll
    for (int mi = 0; mi < 4; mi++)
        #pragma unroll
        for (int ni = 0; ni < 2; ni++)
            wmma::store_matrix_sync(
                &g_xin[(m0 + wm*64 + mi*16)*(size_t)G_ + n0 + wn*32 + ni*16],
                acc[mi][ni], G_, wmma::mem_row_major);
}

// ---------------- Stage 2: persistent recurrence, 128 co-resident CTAs ----------------
// CTA owns 8 h-cols (32 gate rows, w_hh slice smem-resident). 8 warps = 2(M) x 4(K-split).
__global__ __launch_bounds__(256) void lstm_rec(const float* __restrict__ whh,
                                                const float* __restrict__ bih,
                                                const float* __restrict__ bhh,
                                                float* __restrict__ out,
                                                int layer) {
    extern __shared__ float sm[];
    float* Ws   = sm;
    float* Hs   = sm + OFF_HS;
    float* Ps   = sm + OFF_PS;
    float* Cs   = sm + OFF_CS;
    float* Bsum = sm + OFF_BS;

    const int tid  = threadIdx.x;
    const int warp = tid >> 5;
    const int lane = tid & 31;
    const int wm   = warp & 1;            // batch half (32 rows)
    const int wk   = warp >> 1;           // K quarter within each chunk
    const int j0   = blockIdx.x * 8;

    const float* whh_l = whh + (size_t)layer * (size_t)G_ * H_;
    const float* bih_l = bih + (size_t)layer * G_;
    const float* bhh_l = bhh + (size_t)layer * G_;
    float* seq_out = (layer == 0) ? g_seq0 : out;
    float* hn_out  = out + TBH + (size_t)layer * BH;
    float* cn_out  = out + TBH + 2*(size_t)BH + (size_t)layer * BH;

    // Stage w_hh rows (n = gate*8 + jj), tf32-rounded.
    #pragma unroll 4
    for (int i = 0; i < 32; i++) {
        int idx = i*256 + tid;            // 8192 float4
        int r = idx >> 8;
        int c = (idx & 255) << 2;
        int grow = (r >> 3) * H_ + j0 + (r & 7);
        float4 v = *reinterpret_cast<const float4*>(&whh_l[(size_t)grow * H_ + c]);
        v.x = wmma::__float_to_tf32(v.x); v.y = wmma::__float_to_tf32(v.y);
        v.z = wmma::__float_to_tf32(v.z); v.w = wmma::__float_to_tf32(v.w);
        *reinterpret_cast<float4*>(&Ws[r*1032 + c]) = v;
    }
    if (tid < 32) {
        int grow = (tid >> 3) * H_ + j0 + (tid & 7);
        Bsum[tid] = bih_l[grow] + bhh_l[grow];
    }
    Cs[tid] = 0.0f; Cs[tid + 256] = 0.0f;
    __syncthreads();

    const int b0 = tid >> 3,        jj = tid & 7;
    const int b1 = (tid + 256) >> 3;
    const int hr = (tid >> 3) + ((tid & 4) << 3);   // unused helper removed below

    for (int t = 0; t < T_; ++t) {
        const float* hprev = g_h + (size_t)(t & 1) * BH;
        float*       hnext = g_h + (size_t)((t + 1) & 1) * BH;

        // xin prefetch (independent of h)
        float xr[8];
        {
            const float* xb = g_xin + (size_t)t * B_ * G_ + j0 + jj;
            const float* p0 = xb + (size_t)b0 * G_;
            const float* p1 = xb + (size_t)b1 * G_;
            xr[0]=p0[0]; xr[1]=p0[1024]; xr[2]=p0[2048]; xr[3]=p0[3072];
            xr[4]=p1[0]; xr[5]=p1[1024]; xr[6]=p1[2048]; xr[7]=p1[3072];
        }

        wmma::fragment<wmma::accumulator,16,16,8,float> acc[2][2];
        #pragma unroll
        for (int mi = 0; mi < 2; mi++)
            #pragma unroll
            for (int ni = 0; ni < 2; ni++)
                wmma::fill_fragment(acc[mi][ni], 0.0f);

        // prefetch chunk 0 of h into registers (L2-only loads)
        float4 hreg[8];
        #pragma unroll
        for (int i = 0; i < 8; i++) {
            int idx = i*256 + tid;
            int r = idx >> 5, c = (idx & 31) << 2;
            hreg[i] = __ldcg(reinterpret_cast<const float4*>(&hprev[(size_t)r*H_ + c]));
        }

        for (int ch = 0; ch < 8; ch++) {
            const int kc = ch * 128;
            __syncthreads();                     // Hs free
            #pragma unroll
            for (int i = 0; i < 8; i++) {
                int idx = i*256 + tid;
                int r = idx >> 5, c = (idx & 31) << 2;
                float4 v = hreg[i];
                v.x = wmma::__float_to_tf32(v.x); v.y = wmma::__float_to_tf32(v.y);
                v.z = wmma::__float_to_tf32(v.z); v.w = wmma::__float_to_tf32(v.w);
                *reinterpret_cast<float4*>(&Hs[r*136 + c]) = v;
            }
            __syncthreads();                     // Hs ready
            if (ch < 7) {                        // pipeline next chunk load over mma
                #pragma unroll
                for (int i = 0; i < 8; i++) {
                    int idx = i*256 + tid;
                    int r = idx >> 5, c = (idx & 31) << 2;
                    hreg[i] = __ldcg(reinterpret_cast<const float4*>(&hprev[(size_t)r*H_ + kc + 128 + c]));
                }
            }
            #pragma unroll
            for (int k8 = 0; k8 < 4; k8++) {
                const int koff = wk*32 + k8*8;
                wmma::fragment<wmma::matrix_a,16,16,8,wmma::precision::tf32,wmma::row_major> af[2];
                wmma::fragment<wmma::matrix_b,16,16,8,wmma::precision::tf32,wmma::col_major> bf[2];
                wmma::load_matrix_sync(af[0], &Hs[(wm*32     )*136 + koff], 136);
                wmma::load_matrix_sync(af[1], &Hs[(wm*32 + 16)*136 + koff], 136);
                wmma::load_matrix_sync(bf[0], &Ws[             kc + koff], 1032);
                wmma::load_matrix_sync(bf[1], &Ws[16*1032    + kc + koff], 1032);
                #pragma unroll
                for (int mi = 0; mi < 2; mi++)
                    #pragma unroll
                    for (int ni = 0; ni < 2; ni++)
                        wmma::mma_sync(acc[mi][ni], af[mi], bf[ni], acc[mi][ni]);
            }
        }

        // per-warp partials -> Ps[warp] (32x32, stride 36)
        #pragma unroll
        for (int mi = 0; mi < 2; mi++)
            #pragma unroll
            for (int ni = 0; ni < 2; ni++)
                wmma::store_matrix_sync(&Ps[warp*1152 + (mi*16)*36 + ni*16],
                                        acc[mi][ni], 36, wmma::mem_row_major);
        __syncthreads();

        // fused K-reduction + gate epilogue: elements e = tid, tid+256
        #pragma unroll
        for (int h2 = 0; h2 < 2; h2++) {
            int e  = tid + h2*256;
            int b  = e >> 3;
            int wmb = b >> 5, br = b & 31;
            float s[4];
            #pragma unroll
            for (int g = 0; g < 4; g++) {
                int n = g*8 + jj;
                float a = Ps[(0*2+wmb)*1152 + br*36 + n]
                        + Ps[(1*2+wmb)*1152 + br*36 + n]
                        + Ps[(2*2+wmb)*1152 + br*36 + n]
                        + Ps[(3*2+wmb)*1152 + br*36 + n];
                s[g] = a + xr[h2*4 + g] + Bsum[n];
            }
            float si = 1.0f / (1.0f + __expf(-s[0]));
            float sf = 1.0f / (1.0f + __expf(-s[1]));
            float so = 1.0f / (1.0f + __expf(-s[3]));
            float cv = sf * Cs[e] + si * tanhf(s[2]);
            float hv = so * tanhf(cv);
            Cs[e] = cv;
            hnext[(size_t)b*H_ + j0 + jj] = hv;
            seq_out[((size_t)t * B_ + b) * H_ + j0 + jj] = hv;
            if (t == T_ - 1) {
                hn_out[(size_t)b*H_ + j0 + jj] = hv;
                cn_out[(size_t)b*H_ + j0 + jj] = cv;
            }
        }
        __syncthreads();

        // distributed flag barrier: own-slot store + warp-parallel min poll
        if (warp == 0) {
            if (lane == 0) {
                __threadfence();
                *reinterpret_cast<volatile unsigned*>(&g_flag[blockIdx.x]) = (unsigned)(t + 1);
            }
            const unsigned tgt = (unsigned)(t + 1);
            for (;;) {
                unsigned m0 = __ldcg(&g_flag[lane]);
                unsigned m1 = __ldcg(&g_flag[lane + 32]);
                unsigned m2 = __ldcg(&g_flag[lane + 64]);
                unsigned m3 = __ldcg(&g_flag[lane + 96]);
                unsigned mn = min(min(m0, m1), min(m2, m3));
                #pragma unroll
                for (int o = 16; o; o >>= 1)
                    mn = min(mn, __shfl_xor_sync(0xffffffffu, mn, o));
                if (mn >= tgt) break;
                __nanosleep(32);
            }
            __threadfence();
        }
        __syncthreads();
    }
    (void)hr;
}

// ---------------- launch ----------------
extern "C" void kernel_launch(void* const* d_in, const int* in_sizes, int n_in,
                              void* d_out, int out_size) {
    const float* x   = (const float*)d_in[0];
    const float* wih = (const float*)d_in[1];
    const float* whh = (const float*)d_in[2];
    const float* bih = (const float*)d_in[3];
    const float* bhh = (const float*)d_in[4];
    float* out = (float*)d_out;

    cudaFuncSetAttribute(lstm_rec, cudaFuncAttributeMaxDynamicSharedMemorySize, SMEM_BYTES);

    init_kernel<<<128, 256>>>();
    gemm_xin<<<dim3(32, 256), 256>>>(x, wih, 0);
    lstm_rec<<<NCTA, 256, SMEM_BYTES>>>(whh, bih, bhh, out, 0);

    init_kernel<<<128, 256>>>();
    gemm_xin<<<dim3(32, 256), 256>>>(x, wih, 1);
    lstm_rec<<<NCTA, 256, SMEM_BYTES>>>(whh, bih, bhh, out, 1);
}